// round 8
// baseline (speedup 1.0000x reference)
#include <cuda_runtime.h>
#include <math.h>
#include <stdint.h>

#define A_N 49104
#define B_N 8
#define C_N 80
#define K_N 256
#define IMG 512.0f
#define ROW4 20                 // 80 floats = 20 float4 per anchor
#define CH 1024                 // anchors per chunk
#define NCH 48                  // chunks per batch (48*1024 >= 49104)

typedef unsigned long long u64;

// -------- device scratch --------
__device__ u64 g_cand[B_N * NCH * K_N];   // chunk top-256 lists
__device__ u64 g_oct [B_N * 8 * K_N];     // octet top-256 lists

// ============================================================
// warp-level helpers for register bitonic sort (desc)
// ============================================================
__device__ __forceinline__ void cx_reg(u64& a, u64& b, bool desc) {
    u64 lo = (a < b) ? a : b;
    u64 hi = (a < b) ? b : a;
    a = desc ? hi : lo;
    b = desc ? lo : hi;
}
__device__ __forceinline__ u64 cx_shfl(u64 v, int j, bool desc, int lane) {
    u64 pv = __shfl_xor_sync(0xffffffffu, v, j);
    bool lower = (lane & j) == 0;
    bool keepmax = (desc == lower);
    u64 mx = (v > pv) ? v : pv;
    u64 mn = (v > pv) ? pv : v;
    return keepmax ? mx : mn;
}

// ============================================================
// K1: fused score + chunk top-256.  CH=1024, 512 threads.
//   16 warps register-sort 64 keys each, then smem merges:
//   16x64 -> 8x128 -> 4x256 -> truncating -> top-256.
// ============================================================
__global__ __launch_bounds__(512) void k_topk_local(const float* __restrict__ cls) {
    __shared__ u64 sk[CH];
    const int tid = threadIdx.x;
    const int lane = tid & 31;
    const int w = tid >> 5;                 // warp 0..15
    const int b = blockIdx.x / NCH;
    const int c = blockIdx.x % NCH;
    const int base = c * CH;
    const float4* cls4 = reinterpret_cast<const float4*>(cls) + (size_t)b * A_N * ROW4;

    // ---- scores: 4 threads per anchor, 8 iterations ----
#pragma unroll
    for (int it = 0; it < (CH * 4) / 512; it++) {
        int task = it * 512 + tid;
        int al = task >> 2;
        int j = task & 3;
        int a = base + al;
        float m = -INFINITY;
        if (a < A_N) {
            const float4* row = cls4 + (size_t)a * ROW4 + j;
#pragma unroll
            for (int i = 0; i < 5; i++) {
                float4 v = row[i * 4];
                m = fmaxf(m, fmaxf(fmaxf(v.x, v.y), fmaxf(v.z, v.w)));
            }
        }
        m = fmaxf(m, __shfl_xor_sync(0xffffffffu, m, 1));
        m = fmaxf(m, __shfl_xor_sync(0xffffffffu, m, 2));
        if (j == 0) {
            u64 key = 0ull;
            if (a < A_N) {
                float score = 1.0f / (1.0f + expf(-m));
                if (!(score > 0.01f)) score = 0.0f;
                key = ((u64)__float_as_uint(score) << 32) |
                      (u64)(0xFFFFFFFFu - (unsigned)a);
            }
            sk[al] = key;
        }
    }
    __syncthreads();

    // ---- register bitonic sort: each warp sorts 64 keys desc ----
    u64 v[2];
#pragma unroll
    for (int r = 0; r < 2; r++) v[r] = sk[w * 64 + r * 32 + lane];

    for (int k = 2; k <= 64; k <<= 1) {
        for (int j = k >> 1; j >= 1; j >>= 1) {
            if (j >= 32) {
                int jr = j >> 5;   // == 1
#pragma unroll
                for (int r = 0; r < 2; r++) {
                    if ((r & jr) == 0) {
                        bool desc = (((r * 32) & k) == 0);
                        cx_reg(v[r], v[r | jr], desc);
                    }
                }
            } else {
#pragma unroll
                for (int r = 0; r < 2; r++) {
                    bool desc = (k >= 32) ? (((r * 32) & k) == 0)
                                          : ((lane & k) == 0);
                    v[r] = cx_shfl(v[r], j, desc, lane);
                }
            }
        }
    }
#pragma unroll
    for (int r = 0; r < 2; r++) sk[w * 64 + r * 32 + lane] = v[r];
    __syncthreads();

    // ---- L1: full merge 16x64 -> 8x128 ----
    {
        int p = tid >> 6, i = tid & 63;
        int e = p * 128 + i, f = p * 128 + 127 - i;
        u64 x = sk[e], y = sk[f];
        if (x < y) { sk[e] = y; sk[f] = x; }
    }
    __syncthreads();
    for (int j = 32; j >= 1; j >>= 1) {
        int p = tid >> 6, i = tid & 63;
        int e = p * 128 + (((i & ~(j - 1)) << 1) | (i & (j - 1)));
        int f = e + j;
        u64 x = sk[e], y = sk[f];
        if (x < y) { sk[e] = y; sk[f] = x; }
        __syncthreads();
    }

    // ---- L2: full merge 8x128 -> 4x256 ----
    {
        int p = tid >> 7, i = tid & 127;
        int e = p * 256 + i, f = p * 256 + 255 - i;
        u64 x = sk[e], y = sk[f];
        if (x < y) { sk[e] = y; sk[f] = x; }
    }
    __syncthreads();
    for (int j = 64; j >= 1; j >>= 1) {
        int p = tid >> 7, i = tid & 127;
        int e = p * 256 + (((i & ~(j - 1)) << 1) | (i & (j - 1)));
        int f = e + j;
        u64 x = sk[e], y = sk[f];
        if (x < y) { sk[e] = y; sk[f] = x; }
        __syncthreads();
    }

    // ---- truncating merges 4 -> 1 (2 levels), keep top-256 ----
    for (int lvl = 0; lvl < 2; lvl++) {
        int npair = 2 >> lvl;               // 2, 1
        int stride = 512 << lvl;
        for (int t = tid; t < npair * 256; t += 512) {
            int p = t >> 8, i = t & 255;
            int A = p * stride, B = A + (stride >> 1);
            u64 x = sk[A + i], y = sk[B + 255 - i];
            if (y > x) sk[A + i] = y;
        }
        __syncthreads();
        for (int j = 128; j >= 1; j >>= 1) {
            int ncmp = npair * 128;
            for (int t = tid; t < ncmp; t += 512) {
                int p = t >> 7, i = t & 127;
                int A = p * stride;
                int e = A + (((i & ~(j - 1)) << 1) | (i & (j - 1)));
                int f = e + j;
                u64 x = sk[e], y = sk[f];
                if (x < y) { sk[e] = y; sk[f] = x; }
            }
            __syncthreads();
        }
    }

    if (tid < K_N)
        g_cand[blockIdx.x * K_N + tid] = sk[tid];
}

// ============================================================
// K2a: merge 6 chunk-lists -> one top-256. grid = B_N*8.
// ============================================================
__global__ __launch_bounds__(512) void k_merge() {
    __shared__ u64 keys[2048];
    const int tid = threadIdx.x;
    const int b = blockIdx.x >> 3;
    const int o = blockIdx.x & 7;

    for (int i = tid; i < 2048; i += 512) {
        int l = i >> 8;
        keys[i] = (l < 6) ? g_cand[(b * NCH + o * 6 + l) * K_N + (i & 255)] : 0ull;
    }
    __syncthreads();

#pragma unroll
    for (int lvl = 0; lvl < 3; lvl++) {
        int npair = 4 >> lvl;
        for (int t = tid; t < npair * 256; t += 512) {
            int p = t >> 8, i = t & 255;
            int A = p * (512 << lvl), B = A + (256 << lvl);
            u64 x = keys[A + i], y = keys[B + 255 - i];
            if (y > x) keys[A + i] = y;
        }
        __syncthreads();
        for (int j = 128; j >= 1; j >>= 1) {
            for (int t = tid; t < npair * 128; t += 512) {
                int p = t >> 7, i = t & 127;
                int seg = p * (512 << lvl);
                int e = seg + (((i & ~(j - 1)) << 1) | (i & (j - 1)));
                int f = e + j;
                u64 x = keys[e], y = keys[f];
                if (x < y) { keys[e] = y; keys[f] = x; }
            }
            __syncthreads();
        }
    }

    if (tid < K_N)
        g_oct[blockIdx.x * K_N + tid] = keys[tid];
}

// ============================================================
// K2b: merge 8 octet lists + gather/decode + NMS (Jacobi) + output.
// ============================================================
__global__ __launch_bounds__(1024) void k_final(const float* __restrict__ cls,
                                                const float* __restrict__ regs,
                                                const float* __restrict__ anchors,
                                                float* __restrict__ out,
                                                int out_size) {
    const int b = blockIdx.x;
    const int tid = threadIdx.x;

    __shared__ u64 keys[2048];
    __shared__ float4 bx[K_N];
    __shared__ float sc[K_N];
    __shared__ int lb[K_N];
    __shared__ unsigned msk[K_N][8];
    __shared__ unsigned keepw[8];
    __shared__ int changed;

    for (int i = tid; i < 2048; i += 1024)
        keys[i] = g_oct[b * 8 * K_N + i];
    __syncthreads();

    // 3 truncating merge levels: 8 lists -> 1
#pragma unroll
    for (int lvl = 0; lvl < 3; lvl++) {
        int npair = 4 >> lvl;
        for (int t = tid; t < npair * 256; t += 1024) {
            int p = t >> 8, i = t & 255;
            int A = p * (512 << lvl), B = A + (256 << lvl);
            u64 x = keys[A + i], y = keys[B + 255 - i];
            if (y > x) keys[A + i] = y;
        }
        __syncthreads();
        for (int j = 128; j >= 1; j >>= 1) {
            for (int t = tid; t < npair * 128; t += 1024) {
                int p = t >> 7, i = t & 127;
                int seg = p * (512 << lvl);
                int e = seg + (((i & ~(j - 1)) << 1) | (i & (j - 1)));
                int f = e + j;
                u64 x = keys[e], y = keys[f];
                if (x < y) { keys[e] = y; keys[f] = x; }
            }
            __syncthreads();
        }
    }

    // gather: 4 threads per winner recompute argmax; j==0 decodes box
    {
        int e = tid >> 2, j = tid & 3;
        u64 v = keys[e];
        unsigned kbits = (unsigned)(v >> 32);
        unsigned a = 0xFFFFFFFFu - (unsigned)(v & 0xFFFFFFFFu);
        const float4* row = reinterpret_cast<const float4*>(cls) +
                            ((size_t)b * A_N + a) * ROW4;
        float m = -INFINITY;
        int arg = 0;
#pragma unroll
        for (int q0 = 0; q0 < 5; q0++) {
            int q = j + 4 * q0;
            float4 x = row[q];
            int cc = 4 * q;
            if (x.x > m) { m = x.x; arg = cc; }
            if (x.y > m) { m = x.y; arg = cc + 1; }
            if (x.z > m) { m = x.z; arg = cc + 2; }
            if (x.w > m) { m = x.w; arg = cc + 3; }
        }
#pragma unroll
        for (int off = 1; off < 4; off <<= 1) {
            float mo = __shfl_xor_sync(0xffffffffu, m, off);
            int ao = __shfl_xor_sync(0xffffffffu, arg, off);
            if (mo > m || (mo == m && ao < arg)) { m = mo; arg = ao; }
        }
        if (j == 0) {
            sc[e] = __uint_as_float(kbits);
            lb[e] = arg;
            float4 an = reinterpret_cast<const float4*>(anchors)[a];
            float aw = an.z - an.x, ah = an.w - an.y;
            float acx = an.x + 0.5f * aw, acy = an.y + 0.5f * ah;
            float4 rg = reinterpret_cast<const float4*>(regs)[(size_t)b * A_N + a];
            float cx = acx + rg.x * aw;
            float cy = acy + rg.y * ah;
            float dw = fminf(fmaxf(rg.z, -4.0f), 4.0f);
            float dh = fminf(fmaxf(rg.w, -4.0f), 4.0f);
            float ww = aw * expf(dw);
            float hh = ah * expf(dh);
            float x1 = fminf(fmaxf(cx - 0.5f * ww, 0.0f), IMG);
            float y1 = fminf(fmaxf(cy - 0.5f * hh, 0.0f), IMG);
            float x2 = fminf(fmaxf(cx + 0.5f * ww, 0.0f), IMG);
            float y2 = fminf(fmaxf(cy + 0.5f * hh, 0.0f), IMG);
            bx[e] = make_float4(x1, y1, x2, y2);
        }
    }
    __syncthreads();

    // NMS masks: 4 threads per candidate, 64 columns each
    {
        int i = tid >> 2, q = tid & 3;
        float4 me = bx[i];
        float myarea = fmaxf(me.z - me.x, 0.0f) * fmaxf(me.w - me.y, 0.0f);
        unsigned w0 = 0u, w1 = 0u;
        int j0 = q * 64;
#pragma unroll 4
        for (int jj = 0; jj < 64; jj++) {
            float4 o = bx[j0 + jj];
            float ix1 = fmaxf(me.x, o.x);
            float iy1 = fmaxf(me.y, o.y);
            float ix2 = fminf(me.z, o.z);
            float iy2 = fminf(me.w, o.w);
            float iw = fmaxf(ix2 - ix1, 0.0f);
            float ih = fmaxf(iy2 - iy1, 0.0f);
            float inter = iw * ih;
            float oarea = fmaxf(o.z - o.x, 0.0f) * fmaxf(o.w - o.y, 0.0f);
            float uni = myarea + oarea - inter;
            float iou = inter / fmaxf(uni, 1e-8f);
            if (iou > 0.5f) {
                if (jj < 32) w0 |= 1u << jj;
                else w1 |= 1u << (jj - 32);
            }
        }
        msk[i][q * 2 + 0] = w0;
        msk[i][q * 2 + 1] = w1;
    }
    __syncthreads();

    // Jacobi fixpoint NMS keep (== sequential NMS result)
    bool ok = false;
    unsigned mw[8];
    int wi = tid >> 5;
    unsigned below = (1u << (tid & 31)) - 1u;
    if (tid < K_N) {
        ok = sc[tid] > 0.0f;
#pragma unroll
        for (int w = 0; w < 8; w++) mw[w] = msk[tid][w];
        unsigned word = __ballot_sync(0xffffffffu, ok);
        if ((tid & 31) == 0) keepw[wi] = word;
    }
    __syncthreads();

    for (int iter = 0; iter < K_N; iter++) {
        bool newbit = false;
        unsigned oldword = 0u;
        if (tid < K_N) {
            oldword = keepw[wi];
            unsigned sup = 0u;
#pragma unroll
            for (int w = 0; w < 8; w++) {
                unsigned kw = keepw[w];
                unsigned lim = (w < wi) ? 0xFFFFFFFFu : (w == wi ? below : 0u);
                sup |= mw[w] & kw & lim;
            }
            newbit = ok && (sup == 0u);
        }
        __syncthreads();
        if (tid == 512) changed = 0;
        __syncthreads();
        if (tid < K_N) {
            unsigned word = __ballot_sync(0xffffffffu, newbit);
            if ((tid & 31) == 0) {
                if (word != oldword) changed = 1;
                keepw[wi] = word;
            }
        }
        __syncthreads();
        if (!changed) break;
    }

    // output
    if (tid < K_N) {
        bool kp = (keepw[wi] >> (tid & 31)) & 1u;
        float kf = kp ? 1.0f : 0.0f;
        int base = b * K_N + tid;
        float4 me = bx[tid];
        out[base * 5 + 0] = me.x * kf;
        out[base * 5 + 1] = me.y * kf;
        out[base * 5 + 2] = me.z * kf;
        out[base * 5 + 3] = me.w * kf;
        out[base * 5 + 4] = sc[tid] * kf;
        if (out_size >= B_N * K_N * 5 + B_N * K_N)
            out[B_N * K_N * 5 + base] = (float)lb[tid];
        if (out_size >= B_N * K_N * 5 + 2 * B_N * K_N)
            out[B_N * K_N * 5 + B_N * K_N + base] = kf;
    }
}

// ============================================================
extern "C" void kernel_launch(void* const* d_in, const int* in_sizes, int n_in,
                              void* d_out, int out_size) {
    const float* cls = nullptr;
    const float* regs = nullptr;
    const float* anchors = nullptr;
    for (int i = 0; i < n_in; i++) {
        if (in_sizes[i] == B_N * A_N * C_N) cls = (const float*)d_in[i];
        else if (in_sizes[i] == B_N * A_N * 4) regs = (const float*)d_in[i];
        else if (in_sizes[i] == A_N * 4) anchors = (const float*)d_in[i];
    }
    if (!cls || !regs || !anchors) return;

    float* out = (float*)d_out;

    k_topk_local<<<B_N * NCH, 512>>>(cls);
    k_merge<<<B_N * 8, 512>>>();
    k_final<<<B_N, 1024>>>(cls, regs, anchors, out, out_size);
}

// round 9
// speedup vs baseline: 1.0039x; 1.0039x over previous
#include <cuda_runtime.h>
#include <math.h>
#include <stdint.h>

#define A_N 49104
#define B_N 8
#define C_N 80
#define K_N 256
#define IMG 512.0f
#define ROW4 20                 // 80 floats = 20 float4 per anchor
#define CH 1024                 // anchors per chunk
#define NCH 48                  // chunks per batch (48*1024 >= 49104)

typedef unsigned long long u64;

// -------- device scratch --------
__device__ u64 g_cand[B_N * NCH * K_N];   // chunk top-256 lists
__device__ u64 g_oct [B_N * 4 * K_N];     // quarter-batch top-256 lists

// ============================================================
// warp-level helpers for register bitonic sort (desc)
// ============================================================
__device__ __forceinline__ void cx_reg(u64& a, u64& b, bool desc) {
    u64 lo = (a < b) ? a : b;
    u64 hi = (a < b) ? b : a;
    a = desc ? hi : lo;
    b = desc ? lo : hi;
}
__device__ __forceinline__ u64 cx_shfl(u64 v, int j, bool desc, int lane) {
    u64 pv = __shfl_xor_sync(0xffffffffu, v, j);
    bool lower = (lane & j) == 0;
    bool keepmax = (desc == lower);
    u64 mx = (v > pv) ? v : pv;
    u64 mn = (v > pv) ? pv : v;
    return keepmax ? mx : mn;
}

// ============================================================
// K1: fused score + chunk top-256.  CH=1024, 512 threads.
//   WARP-LOCAL stream->sort: each warp loads its own 64 anchors,
//   builds keys, and register-sorts immediately (no block sync),
//   so streaming and sorting overlap across warps. Then block-
//   synced smem merges: 16x64 -> 8x128 -> 4x256 -> trunc -> 256.
// ============================================================
__global__ __launch_bounds__(512) void k_topk_local(const float* __restrict__ cls) {
    __shared__ u64 sk[CH];
    const int tid = threadIdx.x;
    const int lane = tid & 31;
    const int w = tid >> 5;                 // warp 0..15
    const int b = blockIdx.x / NCH;
    const int c = blockIdx.x % NCH;
    const int base = c * CH + w * 64;       // this warp's 64 anchors
    const float4* cls4 = reinterpret_cast<const float4*>(cls) + (size_t)b * A_N * ROW4;

    // ---- warp-local scores: 4 threads per anchor, 8 iterations ----
    const int j = lane & 3;
#pragma unroll
    for (int it = 0; it < 8; it++) {
        int al = it * 8 + (lane >> 2);      // 0..63 within warp slice
        int a = base + al;
        float m = -INFINITY;
        if (a < A_N) {
            const float4* row = cls4 + (size_t)a * ROW4 + j;
            float4 v0 = row[0];
            float4 v1 = row[4];
            float4 v2 = row[8];
            float4 v3 = row[12];
            float4 v4 = row[16];
            m = fmaxf(fmaxf(fmaxf(v0.x, v0.y), fmaxf(v0.z, v0.w)),
                fmaxf(fmaxf(fmaxf(v1.x, v1.y), fmaxf(v1.z, v1.w)),
                fmaxf(fmaxf(fmaxf(v2.x, v2.y), fmaxf(v2.z, v2.w)),
                fmaxf(fmaxf(fmaxf(v3.x, v3.y), fmaxf(v3.z, v3.w)),
                      fmaxf(fmaxf(v4.x, v4.y), fmaxf(v4.z, v4.w))))));
        }
        m = fmaxf(m, __shfl_xor_sync(0xffffffffu, m, 1));
        m = fmaxf(m, __shfl_xor_sync(0xffffffffu, m, 2));
        if (j == 0) {
            u64 key = 0ull;
            if (a < A_N) {
                float score = 1.0f / (1.0f + expf(-m));
                if (!(score > 0.01f)) score = 0.0f;
                key = ((u64)__float_as_uint(score) << 32) |
                      (u64)(0xFFFFFFFFu - (unsigned)a);
            }
            sk[w * 64 + al] = key;
        }
    }
    __syncwarp();

    // ---- register bitonic sort: this warp sorts its 64 keys desc ----
    u64 v[2];
    v[0] = sk[w * 64 + lane];
    v[1] = sk[w * 64 + 32 + lane];

    for (int k = 2; k <= 64; k <<= 1) {
        for (int jj = k >> 1; jj >= 1; jj >>= 1) {
            if (jj >= 32) {
                cx_reg(v[0], v[1], (((0) & k) == 0));   // idx bit k: both halves desc for k=64
            } else {
#pragma unroll
                for (int r = 0; r < 2; r++) {
                    bool desc = (k >= 32) ? (((r * 32) & k) == 0)
                                          : ((lane & k) == 0);
                    v[r] = cx_shfl(v[r], jj, desc, lane);
                }
            }
        }
    }
    sk[w * 64 + lane] = v[0];
    sk[w * 64 + 32 + lane] = v[1];
    __syncthreads();

    // ---- L1: full merge 16x64 -> 8x128 ----
    {
        int p = tid >> 6, i = tid & 63;
        int e = p * 128 + i, f = p * 128 + 127 - i;
        u64 x = sk[e], y = sk[f];
        if (x < y) { sk[e] = y; sk[f] = x; }
    }
    __syncthreads();
    for (int jj = 32; jj >= 1; jj >>= 1) {
        int p = tid >> 6, i = tid & 63;
        int e = p * 128 + (((i & ~(jj - 1)) << 1) | (i & (jj - 1)));
        int f = e + jj;
        u64 x = sk[e], y = sk[f];
        if (x < y) { sk[e] = y; sk[f] = x; }
        __syncthreads();
    }

    // ---- L2: full merge 8x128 -> 4x256 ----
    {
        int p = tid >> 7, i = tid & 127;
        int e = p * 256 + i, f = p * 256 + 255 - i;
        u64 x = sk[e], y = sk[f];
        if (x < y) { sk[e] = y; sk[f] = x; }
    }
    __syncthreads();
    for (int jj = 64; jj >= 1; jj >>= 1) {
        int p = tid >> 7, i = tid & 127;
        int e = p * 256 + (((i & ~(jj - 1)) << 1) | (i & (jj - 1)));
        int f = e + jj;
        u64 x = sk[e], y = sk[f];
        if (x < y) { sk[e] = y; sk[f] = x; }
        __syncthreads();
    }

    // ---- truncating merges 4 -> 1 (2 levels), keep top-256 ----
    for (int lvl = 0; lvl < 2; lvl++) {
        int npair = 2 >> lvl;
        int stride = 512 << lvl;
        for (int t = tid; t < npair * 256; t += 512) {
            int p = t >> 8, i = t & 255;
            int A = p * stride, B = A + (stride >> 1);
            u64 x = sk[A + i], y = sk[B + 255 - i];
            if (y > x) sk[A + i] = y;
        }
        __syncthreads();
        for (int jj = 128; jj >= 1; jj >>= 1) {
            int ncmp = npair * 128;
            for (int t = tid; t < ncmp; t += 512) {
                int p = t >> 7, i = t & 127;
                int A = p * stride;
                int e = A + (((i & ~(jj - 1)) << 1) | (i & (jj - 1)));
                int f = e + jj;
                u64 x = sk[e], y = sk[f];
                if (x < y) { sk[e] = y; sk[f] = x; }
            }
            __syncthreads();
        }
    }

    if (tid < K_N)
        g_cand[blockIdx.x * K_N + tid] = sk[tid];
}

// ============================================================
// K2a: merge 12 chunk-lists -> one top-256. grid = B_N*4.
// ============================================================
__global__ __launch_bounds__(512) void k_merge() {
    __shared__ u64 keys[4096];
    const int tid = threadIdx.x;
    const int b = blockIdx.x >> 2;
    const int o = blockIdx.x & 3;

    for (int i = tid; i < 4096; i += 512) {
        int l = i >> 8;
        keys[i] = (l < 12) ? g_cand[(b * NCH + o * 12 + l) * K_N + (i & 255)] : 0ull;
    }
    __syncthreads();

    // 4 truncating levels: 16 lists -> 1
#pragma unroll
    for (int lvl = 0; lvl < 4; lvl++) {
        int npair = 8 >> lvl;
        for (int t = tid; t < npair * 256; t += 512) {
            int p = t >> 8, i = t & 255;
            int A = p * (512 << lvl), B = A + (256 << lvl);
            u64 x = keys[A + i], y = keys[B + 255 - i];
            if (y > x) keys[A + i] = y;
        }
        __syncthreads();
        for (int jj = 128; jj >= 1; jj >>= 1) {
            for (int t = tid; t < npair * 128; t += 512) {
                int p = t >> 7, i = t & 127;
                int seg = p * (512 << lvl);
                int e = seg + (((i & ~(jj - 1)) << 1) | (i & (jj - 1)));
                int f = e + jj;
                u64 x = keys[e], y = keys[f];
                if (x < y) { keys[e] = y; keys[f] = x; }
            }
            __syncthreads();
        }
    }

    if (tid < K_N)
        g_oct[blockIdx.x * K_N + tid] = keys[tid];
}

// ============================================================
// K2b: merge 4 lists + gather/decode + NMS (Jacobi) + output.
// ============================================================
__global__ __launch_bounds__(1024) void k_final(const float* __restrict__ cls,
                                                const float* __restrict__ regs,
                                                const float* __restrict__ anchors,
                                                float* __restrict__ out,
                                                int out_size) {
    const int b = blockIdx.x;
    const int tid = threadIdx.x;

    __shared__ u64 keys[1024];
    __shared__ float4 bx[K_N];
    __shared__ float sc[K_N];
    __shared__ int lb[K_N];
    __shared__ unsigned msk[K_N][8];
    __shared__ unsigned keepw[8];
    __shared__ int changed;

    keys[tid] = g_oct[b * 4 * K_N + tid];
    __syncthreads();

    // 2 truncating merge levels: 4 lists -> 1
#pragma unroll
    for (int lvl = 0; lvl < 2; lvl++) {
        int npair = 2 >> lvl;
        for (int t = tid; t < npair * 256; t += 1024) {
            int p = t >> 8, i = t & 255;
            int A = p * (512 << lvl), B = A + (256 << lvl);
            u64 x = keys[A + i], y = keys[B + 255 - i];
            if (y > x) keys[A + i] = y;
        }
        __syncthreads();
        for (int jj = 128; jj >= 1; jj >>= 1) {
            for (int t = tid; t < npair * 128; t += 1024) {
                int p = t >> 7, i = t & 127;
                int seg = p * (512 << lvl);
                int e = seg + (((i & ~(jj - 1)) << 1) | (i & (jj - 1)));
                int f = e + jj;
                u64 x = keys[e], y = keys[f];
                if (x < y) { keys[e] = y; keys[f] = x; }
            }
            __syncthreads();
        }
    }

    // gather: 4 threads per winner recompute argmax; j==0 decodes box
    {
        int e = tid >> 2, j = tid & 3;
        u64 v = keys[e];
        unsigned kbits = (unsigned)(v >> 32);
        unsigned a = 0xFFFFFFFFu - (unsigned)(v & 0xFFFFFFFFu);
        const float4* row = reinterpret_cast<const float4*>(cls) +
                            ((size_t)b * A_N + a) * ROW4;
        float m = -INFINITY;
        int arg = 0;
#pragma unroll
        for (int q0 = 0; q0 < 5; q0++) {
            int q = j + 4 * q0;
            float4 x = row[q];
            int cc = 4 * q;
            if (x.x > m) { m = x.x; arg = cc; }
            if (x.y > m) { m = x.y; arg = cc + 1; }
            if (x.z > m) { m = x.z; arg = cc + 2; }
            if (x.w > m) { m = x.w; arg = cc + 3; }
        }
#pragma unroll
        for (int off = 1; off < 4; off <<= 1) {
            float mo = __shfl_xor_sync(0xffffffffu, m, off);
            int ao = __shfl_xor_sync(0xffffffffu, arg, off);
            if (mo > m || (mo == m && ao < arg)) { m = mo; arg = ao; }
        }
        if (j == 0) {
            sc[e] = __uint_as_float(kbits);
            lb[e] = arg;
            float4 an = reinterpret_cast<const float4*>(anchors)[a];
            float aw = an.z - an.x, ah = an.w - an.y;
            float acx = an.x + 0.5f * aw, acy = an.y + 0.5f * ah;
            float4 rg = reinterpret_cast<const float4*>(regs)[(size_t)b * A_N + a];
            float cx = acx + rg.x * aw;
            float cy = acy + rg.y * ah;
            float dw = fminf(fmaxf(rg.z, -4.0f), 4.0f);
            float dh = fminf(fmaxf(rg.w, -4.0f), 4.0f);
            float ww = aw * expf(dw);
            float hh = ah * expf(dh);
            float x1 = fminf(fmaxf(cx - 0.5f * ww, 0.0f), IMG);
            float y1 = fminf(fmaxf(cy - 0.5f * hh, 0.0f), IMG);
            float x2 = fminf(fmaxf(cx + 0.5f * ww, 0.0f), IMG);
            float y2 = fminf(fmaxf(cy + 0.5f * hh, 0.0f), IMG);
            bx[e] = make_float4(x1, y1, x2, y2);
        }
    }
    __syncthreads();

    // NMS masks: 4 threads per candidate, 64 columns each
    {
        int i = tid >> 2, q = tid & 3;
        float4 me = bx[i];
        float myarea = fmaxf(me.z - me.x, 0.0f) * fmaxf(me.w - me.y, 0.0f);
        unsigned w0 = 0u, w1 = 0u;
        int j0 = q * 64;
#pragma unroll 4
        for (int jj = 0; jj < 64; jj++) {
            float4 o = bx[j0 + jj];
            float ix1 = fmaxf(me.x, o.x);
            float iy1 = fmaxf(me.y, o.y);
            float ix2 = fminf(me.z, o.z);
            float iy2 = fminf(me.w, o.w);
            float iw = fmaxf(ix2 - ix1, 0.0f);
            float ih = fmaxf(iy2 - iy1, 0.0f);
            float inter = iw * ih;
            float oarea = fmaxf(o.z - o.x, 0.0f) * fmaxf(o.w - o.y, 0.0f);
            float uni = myarea + oarea - inter;
            float iou = inter / fmaxf(uni, 1e-8f);
            if (iou > 0.5f) {
                if (jj < 32) w0 |= 1u << jj;
                else w1 |= 1u << (jj - 32);
            }
        }
        msk[i][q * 2 + 0] = w0;
        msk[i][q * 2 + 1] = w1;
    }
    __syncthreads();

    // Jacobi fixpoint NMS keep (== sequential NMS result)
    bool ok = false;
    unsigned mw[8];
    int wi = tid >> 5;
    unsigned below = (1u << (tid & 31)) - 1u;
    if (tid < K_N) {
        ok = sc[tid] > 0.0f;
#pragma unroll
        for (int w = 0; w < 8; w++) mw[w] = msk[tid][w];
        unsigned word = __ballot_sync(0xffffffffu, ok);
        if ((tid & 31) == 0) keepw[wi] = word;
    }
    __syncthreads();

    for (int iter = 0; iter < K_N; iter++) {
        bool newbit = false;
        unsigned oldword = 0u;
        if (tid < K_N) {
            oldword = keepw[wi];
            unsigned sup = 0u;
#pragma unroll
            for (int w = 0; w < 8; w++) {
                unsigned kw = keepw[w];
                unsigned lim = (w < wi) ? 0xFFFFFFFFu : (w == wi ? below : 0u);
                sup |= mw[w] & kw & lim;
            }
            newbit = ok && (sup == 0u);
        }
        __syncthreads();
        if (tid == 512) changed = 0;
        __syncthreads();
        if (tid < K_N) {
            unsigned word = __ballot_sync(0xffffffffu, newbit);
            if ((tid & 31) == 0) {
                if (word != oldword) changed = 1;
                keepw[wi] = word;
            }
        }
        __syncthreads();
        if (!changed) break;
    }

    // output
    if (tid < K_N) {
        bool kp = (keepw[wi] >> (tid & 31)) & 1u;
        float kf = kp ? 1.0f : 0.0f;
        int base = b * K_N + tid;
        float4 me = bx[tid];
        out[base * 5 + 0] = me.x * kf;
        out[base * 5 + 1] = me.y * kf;
        out[base * 5 + 2] = me.z * kf;
        out[base * 5 + 3] = me.w * kf;
        out[base * 5 + 4] = sc[tid] * kf;
        if (out_size >= B_N * K_N * 5 + B_N * K_N)
            out[B_N * K_N * 5 + base] = (float)lb[tid];
        if (out_size >= B_N * K_N * 5 + 2 * B_N * K_N)
            out[B_N * K_N * 5 + B_N * K_N + base] = kf;
    }
}

// ============================================================
extern "C" void kernel_launch(void* const* d_in, const int* in_sizes, int n_in,
                              void* d_out, int out_size) {
    const float* cls = nullptr;
    const float* regs = nullptr;
    const float* anchors = nullptr;
    for (int i = 0; i < n_in; i++) {
        if (in_sizes[i] == B_N * A_N * C_N) cls = (const float*)d_in[i];
        else if (in_sizes[i] == B_N * A_N * 4) regs = (const float*)d_in[i];
        else if (in_sizes[i] == A_N * 4) anchors = (const float*)d_in[i];
    }
    if (!cls || !regs || !anchors) return;

    float* out = (float*)d_out;

    k_topk_local<<<B_N * NCH, 512>>>(cls);
    k_merge<<<B_N * 4, 512>>>();
    k_final<<<B_N, 1024>>>(cls, regs, anchors, out, out_size);
}